// round 4
// baseline (speedup 1.0000x reference)
#include <cuda_runtime.h>

#define BB 64
#define SS 512
#define HH 1024
#define LL 64
#define NEM (BB * SS * LL)   // 2097152 emission elements

__device__ float g_em[NEM];    // emissions scratch [B*S, L]
__device__ float g_llh[BB];
__device__ float g_loss;

// ---------------------------------------------------------------------------
// GEMM: em[m][l] = sum_h hs[m][h] * W[h][l] + bias[l],  m in [0, 32768)
// 512 blocks x 256 threads, 64x64 tile, K-tile 32, 4x4 micro-tile.
// ---------------------------------------------------------------------------
__global__ __launch_bounds__(256) void gemm_kernel(
    const float* __restrict__ hs, const float* __restrict__ W,
    const float* __restrict__ bias, float* __restrict__ out_em)
{
    __shared__ float As[32][65];   // [k][m], padded (odd stride -> conflict-free)
    __shared__ float Bs[32][64];   // [k][n]

    const int tid = threadIdx.x;
    const int tm = tid >> 4;
    const int tn = tid & 15;
    const int m0 = blockIdx.x * 64;

    float acc[4][4];
#pragma unroll
    for (int r = 0; r < 4; r++)
#pragma unroll
        for (int c = 0; c < 4; c++) acc[r][c] = 0.f;

    for (int k0 = 0; k0 < HH; k0 += 32) {
        __syncthreads();
#pragma unroll
        for (int i = tid; i < 64 * 32; i += 256) {
            int row = i >> 5;
            int col = i & 31;
            As[col][row] = hs[(size_t)(m0 + row) * HH + (k0 + col)];
        }
#pragma unroll
        for (int i = tid; i < 32 * 64; i += 256) {
            int r = i >> 6;
            int c = i & 63;
            Bs[r][c] = W[(size_t)(k0 + r) * LL + c];
        }
        __syncthreads();

#pragma unroll 8
        for (int kk = 0; kk < 32; kk++) {
            float a0 = As[kk][tm * 4 + 0];
            float a1 = As[kk][tm * 4 + 1];
            float a2 = As[kk][tm * 4 + 2];
            float a3 = As[kk][tm * 4 + 3];
            float b0 = Bs[kk][tn * 4 + 0];
            float b1 = Bs[kk][tn * 4 + 1];
            float b2 = Bs[kk][tn * 4 + 2];
            float b3 = Bs[kk][tn * 4 + 3];
            acc[0][0] = fmaf(a0, b0, acc[0][0]);
            acc[0][1] = fmaf(a0, b1, acc[0][1]);
            acc[0][2] = fmaf(a0, b2, acc[0][2]);
            acc[0][3] = fmaf(a0, b3, acc[0][3]);
            acc[1][0] = fmaf(a1, b0, acc[1][0]);
            acc[1][1] = fmaf(a1, b1, acc[1][1]);
            acc[1][2] = fmaf(a1, b2, acc[1][2]);
            acc[1][3] = fmaf(a1, b3, acc[1][3]);
            acc[2][0] = fmaf(a2, b0, acc[2][0]);
            acc[2][1] = fmaf(a2, b1, acc[2][1]);
            acc[2][2] = fmaf(a2, b2, acc[2][2]);
            acc[2][3] = fmaf(a2, b3, acc[2][3]);
            acc[3][0] = fmaf(a3, b0, acc[3][0]);
            acc[3][1] = fmaf(a3, b1, acc[3][1]);
            acc[3][2] = fmaf(a3, b2, acc[3][2]);
            acc[3][3] = fmaf(a3, b3, acc[3][3]);
        }
    }

    float bj[4];
#pragma unroll
    for (int c = 0; c < 4; c++) bj[c] = bias[tn * 4 + c];
#pragma unroll
    for (int r = 0; r < 4; r++) {
        size_t row = (size_t)(m0 + tm * 4 + r) * LL + tn * 4;
#pragma unroll
        for (int c = 0; c < 4; c++) out_em[row + c] = acc[r][c] + bj[c];
    }
}

// ---------------------------------------------------------------------------
// CRF per batch. labels are INT32 (JAX x64 disabled -> astype(int64) is a
// no-op). All label-derived indices clamped to [0, LL) as defense-in-depth.
// ---------------------------------------------------------------------------
__device__ __forceinline__ int tag_of(int x) {
    int t = (x == -100) ? 0 : x;
    return max(0, min(LL - 1, t));
}

__global__ __launch_bounds__(128) void crf_kernel(
    const float* __restrict__ em_all,
    const int* __restrict__ mask,
    const int* __restrict__ labels,
    const float* __restrict__ start_t,
    const float* __restrict__ end_t,
    const float* __restrict__ trans)
{
    const int b = blockIdx.x;
    const int tid = threadIdx.x;
    const int j = tid & 63;
    const int h = tid >> 6;

    const float* em = em_all + (size_t)b * (SS * LL);
    const int* msk = mask + b * SS;
    const int* lab = labels + (size_t)b * SS;

    __shared__ float u_sh[64];
    __shared__ float part_sh[128];
    __shared__ float red[128];
    __shared__ int len_sh;
    __shared__ float num_sh;

    // ---- sequence length (mask is a contiguous prefix) ----
    int cnt = 0;
    for (int t = tid; t < SS; t += 128) cnt += msk[t];
    red[tid] = (float)cnt;
    __syncthreads();
#pragma unroll
    for (int s = 64; s > 0; s >>= 1) {
        if (tid < s) red[tid] += red[tid + s];
        __syncthreads();
    }
    if (tid == 0) len_sh = max(1, min(SS, (int)(red[0] + 0.5f)));
    __syncthreads();
    const int len = len_sh;

    // ---- numerator ----
    float nsum = 0.f;
    for (int t = 1 + tid; t < len; t += 128) {
        int tp = tag_of(lab[t - 1]);
        int tc = tag_of(lab[t]);
        nsum += trans[tp * LL + tc] + em[t * LL + tc];
    }
    __syncthreads();
    red[tid] = nsum;
    __syncthreads();
#pragma unroll
    for (int s = 64; s > 0; s >>= 1) {
        if (tid < s) red[tid] += red[tid + s];
        __syncthreads();
    }
    if (tid == 0) {
        int t0 = tag_of(lab[0]);
        int tl = tag_of(lab[len - 1]);
        num_sh = start_t[t0] + em[t0] + red[0] + end_t[tl];
    }

    // ---- P[i][j] = exp(trans[i][j]) for this thread's K-half ----
    float P[32];
#pragma unroll
    for (int i2 = 0; i2 < 32; i2++)
        P[i2] = __expf(trans[(h * 32 + i2) * LL + j]);

    // ---- forward recurrence (factored logsumexp, shift = running alpha[0]) ----
    float a = start_t[j] + em[j];
    float shift = start_t[0] + em[0];
    float em_next = 0.f, em0_next = 0.f;
    if (len > 1) { em_next = em[LL + j]; em0_next = em[LL]; }

    for (int t = 1; t < len; t++) {
        float u = __expf(a - shift);
        if (h == 0) u_sh[j] = u;
        __syncthreads();

        float em_cur = em_next, em0_cur = em0_next;
        if (t + 1 < len) {
            em_next = em[(size_t)(t + 1) * LL + j];
            em0_next = em[(size_t)(t + 1) * LL];
        }

        float s0 = 0.f, s1 = 0.f;
        const float* ub = u_sh + h * 32;
#pragma unroll
        for (int q = 0; q < 16; q++) {
            s0 = fmaf(ub[2 * q + 0], P[2 * q + 0], s0);
            s1 = fmaf(ub[2 * q + 1], P[2 * q + 1], s1);
        }
        part_sh[h * 64 + j] = s0 + s1;
        __syncthreads();

        float v = part_sh[j] + part_sh[64 + j];
        float v0 = part_sh[0] + part_sh[64];
        a = em_cur + shift + __logf(v);
        shift = em0_cur + shift + __logf(v0);   // new alpha[0], same arithmetic
    }

    // ---- log Z ----
    red[tid] = (h == 0) ? __expf(a + end_t[j] - shift) : 0.f;
    __syncthreads();
#pragma unroll
    for (int s = 64; s > 0; s >>= 1) {
        if (tid < s) red[tid] += red[tid + s];
        __syncthreads();
    }
    if (tid == 0) {
        float log_z = __logf(red[0]) + shift;
        g_llh[b] = num_sh - log_z;
    }
}

// ---------------------------------------------------------------------------
__global__ void loss_kernel() {
    int t = threadIdx.x;   // 32 threads
    float v = g_llh[t] + g_llh[t + 32];
#pragma unroll
    for (int o = 16; o > 0; o >>= 1) v += __shfl_down_sync(0xffffffffu, v, o);
    if (t == 0) g_loss = -v * (1.0f / BB);
}

// ---------------------------------------------------------------------------
// Writes EXACTLY out_size elements.
//   out_size >  NEM : out[0]=loss, out[1..]=emissions
//   out_size == NEM : emissions only
//   out_size <  NEM : out[0]=loss, rest (if any) zero-filled
// ---------------------------------------------------------------------------
__global__ __launch_bounds__(256) void writeout_kernel(
    float* __restrict__ out, int out_size, int em_off)
{
    int i = blockIdx.x * 256 + threadIdx.x;
    if (i >= out_size) return;
    if (em_off == 1 && i == 0) { out[0] = g_loss; return; }
    int src = i - em_off;
    out[i] = (src < NEM) ? g_em[src] : 0.f;
}

// ---------------------------------------------------------------------------
extern "C" void kernel_launch(void* const* d_in, const int* in_sizes, int n_in,
                              void* d_out, int out_size)
{
    const float* hs      = (const float*)d_in[0];   // [B,S,H] f32
    const int* mask      = (const int*)d_in[1];     // [B,S]   i32
    const int* labels    = (const int*)d_in[2];     // [B,S]   i32 (JAX x64 off)
    const float* W       = (const float*)d_in[3];   // [H,L]   f32
    const float* bias    = (const float*)d_in[4];   // [L]
    const float* start_t = (const float*)d_in[5];   // [L]
    const float* end_t   = (const float*)d_in[6];   // [L]
    const float* trans   = (const float*)d_in[7];   // [L,L]
    float* out = (float*)d_out;

    float* em_scratch = nullptr;
    cudaGetSymbolAddress((void**)&em_scratch, g_em);

    gemm_kernel<<<512, 256>>>(hs, W, bias, em_scratch);
    crf_kernel<<<BB, 128>>>(em_scratch, mask, labels, start_t, end_t, trans);
    loss_kernel<<<1, 32>>>();

    int em_off = (out_size == NEM) ? 0 : 1;
    int grid = (out_size + 255) / 256;
    writeout_kernel<<<grid, 256>>>(out, out_size, em_off);
}